// round 1
// baseline (speedup 1.0000x reference)
#include <cuda_runtime.h>

#define N_NODES 50000
#define N_EDGES 800000
#define DIM 128

// Scratch (device globals — no allocations allowed)
__device__ float g_deg[N_NODES];
__device__ float g_dinv[N_NODES];
__device__ float g_tmp[N_NODES * DIM];   // GEMM output (pre-aggregation)
__device__ float g_h[N_NODES * DIM];     // layer-1 aggregated output (pre-relu)

// ---------------- degree / norm ----------------
__global__ void k_deg_init() {
    int i = blockIdx.x * blockDim.x + threadIdx.x;
    if (i < N_NODES) g_deg[i] = 1.0f;   // self-loop
}

__global__ void k_deg_edges(const int* __restrict__ ei) {
    int e = blockIdx.x * blockDim.x + threadIdx.x;
    if (e < N_EDGES) atomicAdd(&g_deg[ei[N_EDGES + e]], 1.0f);
}

__global__ void k_dinv() {
    int i = blockIdx.x * blockDim.x + threadIdx.x;
    if (i < N_NODES) g_dinv[i] = rsqrtf(g_deg[i]);
}

// ---------------- GEMM: Out[N,128] = act(X)[N,128] @ W[128,128] ----------------
// Block: 64 rows x 128 cols, 256 threads, register tile 4x8.
// Thread (tr = tid/16, tc = tid%16): rows tr*4..+3, cols {tc*4..+3, 64+tc*4..+3}.
template<bool RELU>
__global__ void k_gemm(const float* __restrict__ X, const float* __restrict__ W,
                       float* __restrict__ Out) {
    __shared__ float sW[32][DIM];     // 16 KB   (k-tile x cols)
    __shared__ float sX[32][68];      // 8.7 KB  (k-tile x rows, padded)

    int tid = threadIdx.x;
    int tc = tid & 15, tr = tid >> 4;
    int row0 = blockIdx.x * 64;

    float acc[4][8];
#pragma unroll
    for (int r = 0; r < 4; r++)
#pragma unroll
        for (int c = 0; c < 8; c++) acc[r][c] = 0.f;

    for (int kk = 0; kk < DIM; kk += 32) {
        // load W k-tile (32x128 = 4096 floats, 16 per thread)
#pragma unroll
        for (int i = 0; i < 4; i++) {
            int lin = (i * 256 + tid) * 4;
            int k = lin >> 7, c = lin & 127;
            *(float4*)&sW[k][c] = *(const float4*)&W[(kk + k) * DIM + c];
        }
        // load X tile transposed (64 rows x 32 k), 8 floats per thread
#pragma unroll
        for (int i = 0; i < 2; i++) {
            int lin = (i * 256 + tid) * 4;
            int r = lin >> 5, c = lin & 31;
            int row = row0 + r;
            float4 v = make_float4(0.f, 0.f, 0.f, 0.f);
            if (row < N_NODES) v = *(const float4*)&X[row * DIM + kk + c];
            if (RELU) {
                v.x = fmaxf(v.x, 0.f); v.y = fmaxf(v.y, 0.f);
                v.z = fmaxf(v.z, 0.f); v.w = fmaxf(v.w, 0.f);
            }
            sX[c + 0][r] = v.x; sX[c + 1][r] = v.y;
            sX[c + 2][r] = v.z; sX[c + 3][r] = v.w;
        }
        __syncthreads();

#pragma unroll
        for (int k = 0; k < 32; k++) {
            float4 w0 = *(float4*)&sW[k][tc * 4];
            float4 w1 = *(float4*)&sW[k][tc * 4 + 64];
            float4 xv = *(float4*)&sX[k][tr * 4];
            float xr[4] = {xv.x, xv.y, xv.z, xv.w};
#pragma unroll
            for (int r = 0; r < 4; r++) {
                acc[r][0] += xr[r] * w0.x; acc[r][1] += xr[r] * w0.y;
                acc[r][2] += xr[r] * w0.z; acc[r][3] += xr[r] * w0.w;
                acc[r][4] += xr[r] * w1.x; acc[r][5] += xr[r] * w1.y;
                acc[r][6] += xr[r] * w1.z; acc[r][7] += xr[r] * w1.w;
            }
        }
        __syncthreads();
    }

#pragma unroll
    for (int r = 0; r < 4; r++) {
        int row = row0 + tr * 4 + r;
        if (row < N_NODES) {
            *(float4*)&Out[row * DIM + tc * 4] =
                make_float4(acc[r][0], acc[r][1], acc[r][2], acc[r][3]);
            *(float4*)&Out[row * DIM + 64 + tc * 4] =
                make_float4(acc[r][4], acc[r][5], acc[r][6], acc[r][7]);
        }
    }
}

// ---------------- aggregation ----------------
// out[i] = tmp[i] * dinv[i]^2 + b   (self-loop contribution + bias)
__global__ void k_agg_init(const float* __restrict__ tmp, const float* __restrict__ b,
                           float* __restrict__ out) {
    int t = blockIdx.x * blockDim.x + threadIdx.x;   // one per float4
    if (t >= N_NODES * DIM / 4) return;
    int node = t >> 5;        // 32 float4 per node
    int c4 = t & 31;
    float d = g_dinv[node];
    float s = d * d;
    float4 v = *(const float4*)&tmp[t * 4];
    float4 bb = *(const float4*)&b[c4 * 4];
    float4 o = make_float4(v.x * s + bb.x, v.y * s + bb.y,
                           v.z * s + bb.z, v.w * s + bb.w);
    *(float4*)&out[t * 4] = o;
}

// one warp per edge: out[dst] += tmp[src] * dinv[src]*dinv[dst]
__global__ void k_agg_edges(const float* __restrict__ tmp, const int* __restrict__ ei,
                            float* __restrict__ out) {
    int w = (int)((blockIdx.x * (unsigned)blockDim.x + threadIdx.x) >> 5);
    int lane = threadIdx.x & 31;
    if (w >= N_EDGES) return;
    int src = ei[w];
    int dst = ei[N_EDGES + w];
    float norm = g_dinv[src] * g_dinv[dst];
    float4 v = *(const float4*)&tmp[src * DIM + lane * 4];
    float4 m = make_float4(v.x * norm, v.y * norm, v.z * norm, v.w * norm);
    atomicAdd((float4*)&out[dst * DIM + lane * 4], m);
}

// ---------------- launch ----------------
extern "C" void kernel_launch(void* const* d_in, const int* in_sizes, int n_in,
                              void* d_out, int out_size) {
    const float* x  = (const float*)d_in[0];
    const int*   ei = (const int*)d_in[1];
    const float* W1 = (const float*)d_in[2];
    const float* b1 = (const float*)d_in[3];
    const float* W2 = (const float*)d_in[4];
    const float* b2 = (const float*)d_in[5];
    float* out = (float*)d_out;

    float* tmp_p; cudaGetSymbolAddress((void**)&tmp_p, g_tmp);
    float* h_p;   cudaGetSymbolAddress((void**)&h_p,   g_h);

    int nthr = 256;
    int nb_nodes = (N_NODES + nthr - 1) / nthr;
    int nb_edges = (N_EDGES + nthr - 1) / nthr;
    int nb_gemm  = (N_NODES + 63) / 64;
    int nb_feat  = (N_NODES * DIM / 4 + nthr - 1) / nthr;
    int nb_eagg  = (N_EDGES * 32 + nthr - 1) / nthr;

    // degree + normalization
    k_deg_init<<<nb_nodes, nthr>>>();
    k_deg_edges<<<nb_edges, nthr>>>(ei);
    k_dinv<<<nb_nodes, nthr>>>();

    // layer 1: tmp = x @ W1 ; h = aggregate(tmp) + b1   (relu deferred to layer-2 load)
    k_gemm<false><<<nb_gemm, nthr>>>(x, W1, tmp_p);
    k_agg_init<<<nb_feat, nthr>>>(tmp_p, b1, h_p);
    k_agg_edges<<<nb_eagg, nthr>>>(tmp_p, ei, h_p);

    // layer 2: tmp = relu(h) @ W2 ; out = aggregate(tmp) + b2
    k_gemm<true><<<nb_gemm, nthr>>>(h_p, W2, tmp_p);
    k_agg_init<<<nb_feat, nthr>>>(tmp_p, b2, out);
    k_agg_edges<<<nb_eagg, nthr>>>(tmp_p, ei, out);
}

// round 2
// speedup vs baseline: 1.0981x; 1.0981x over previous
#include <cuda_runtime.h>

#define N_NODES 50000
#define N_EDGES 800000
#define DIM 128

// Scratch (device globals)
__device__ int   g_cnt[N_NODES];
__device__ int   g_off[N_NODES + 1];
__device__ int   g_cur[N_NODES];
__device__ float g_dinv[N_NODES];
__device__ int2  g_edge[N_EDGES];        // {src, norm as float bits} in CSR-by-dst order
__device__ float g_tmp[N_NODES * DIM];   // GEMM output (pre-aggregation)
__device__ float g_h[N_NODES * DIM];     // layer-1 aggregated output (pre-relu)

// ---------------- degree / CSR build ----------------
__global__ void k_zero_cnt() {
    int i = blockIdx.x * blockDim.x + threadIdx.x;
    if (i < N_NODES) g_cnt[i] = 0;
}

__global__ void k_hist(const int* __restrict__ ei) {
    int e = blockIdx.x * blockDim.x + threadIdx.x;
    if (e < N_EDGES) atomicAdd(&g_cnt[ei[N_EDGES + e]], 1);
}

__global__ void k_dinv() {
    int i = blockIdx.x * blockDim.x + threadIdx.x;
    if (i < N_NODES) g_dinv[i] = rsqrtf((float)(g_cnt[i] + 1));  // +1 self-loop
}

__global__ void k_scan() {   // single block, 1024 threads
    __shared__ int sp[1024];
    const int CH = (N_NODES + 1023) / 1024;
    int t = threadIdx.x;
    int base = t * CH;
    int s = 0;
    for (int i = 0; i < CH; i++) {
        int idx = base + i;
        if (idx < N_NODES) s += g_cnt[idx];
    }
    sp[t] = s;
    __syncthreads();
    for (int d = 1; d < 1024; d <<= 1) {
        int v = (t >= d) ? sp[t - d] : 0;
        __syncthreads();
        sp[t] += v;
        __syncthreads();
    }
    int run = (t == 0) ? 0 : sp[t - 1];
    for (int i = 0; i < CH; i++) {
        int idx = base + i;
        if (idx < N_NODES) {
            g_off[idx] = run;
            g_cur[idx] = run;
            run += g_cnt[idx];
        }
    }
    if (t == 1023) g_off[N_NODES] = sp[1023];
}

__global__ void k_scatter(const int* __restrict__ ei) {
    int e = blockIdx.x * blockDim.x + threadIdx.x;
    if (e >= N_EDGES) return;
    int src = ei[e];
    int dst = ei[N_EDGES + e];
    int pos = atomicAdd(&g_cur[dst], 1);
    float norm = g_dinv[src] * g_dinv[dst];
    g_edge[pos] = make_int2(src, __float_as_int(norm));
}

// ---------------- GEMM: Out[N,128] = act(X)[N,128] @ W[128,128] ----------------
// 128x128 block tile, 256 threads, 8x8 register tile per thread.
template<bool RELU>
__global__ void __launch_bounds__(256, 2)
k_gemm(const float* __restrict__ X, const float* __restrict__ W,
       float* __restrict__ Out) {
    __shared__ float sW[16][DIM];    // k-tile x cols  (8 KB)
    __shared__ float sX[16][132];    // k-tile x rows  (padded, 8.25 KB)

    int tid = threadIdx.x;
    int tc = tid & 15, tr = tid >> 4;
    int row0 = blockIdx.x * 128;

    float acc[8][8];
#pragma unroll
    for (int r = 0; r < 8; r++)
#pragma unroll
        for (int c = 0; c < 8; c++) acc[r][c] = 0.f;

    for (int kk = 0; kk < DIM; kk += 16) {
        // W k-tile: 16x128 floats, 2 float4 per thread
#pragma unroll
        for (int i = 0; i < 2; i++) {
            int lin = (i * 256 + tid) * 4;
            int k = lin >> 7, c = lin & 127;
            *(float4*)&sW[k][c] = *(const float4*)&W[(kk + k) * DIM + c];
        }
        // X tile transposed: 128 rows x 16 k, 2 float4 per thread
#pragma unroll
        for (int i = 0; i < 2; i++) {
            int lin = (i * 256 + tid) * 4;
            int r = lin >> 4, c = lin & 15;
            int row = row0 + r;
            float4 v = make_float4(0.f, 0.f, 0.f, 0.f);
            if (row < N_NODES) v = *(const float4*)&X[row * DIM + kk + c];
            if (RELU) {
                v.x = fmaxf(v.x, 0.f); v.y = fmaxf(v.y, 0.f);
                v.z = fmaxf(v.z, 0.f); v.w = fmaxf(v.w, 0.f);
            }
            sX[c + 0][r] = v.x; sX[c + 1][r] = v.y;
            sX[c + 2][r] = v.z; sX[c + 3][r] = v.w;
        }
        __syncthreads();

#pragma unroll
        for (int k = 0; k < 16; k++) {
            float a[8], b[8];
            *(float4*)&b[0] = *(float4*)&sW[k][tc * 4];
            *(float4*)&b[4] = *(float4*)&sW[k][tc * 4 + 64];
            *(float4*)&a[0] = *(float4*)&sX[k][tr * 8];
            *(float4*)&a[4] = *(float4*)&sX[k][tr * 8 + 4];
#pragma unroll
            for (int r = 0; r < 8; r++)
#pragma unroll
                for (int c = 0; c < 8; c++)
                    acc[r][c] += a[r] * b[c];
        }
        __syncthreads();
    }

#pragma unroll
    for (int r = 0; r < 8; r++) {
        int row = row0 + tr * 8 + r;
        if (row < N_NODES) {
            *(float4*)&Out[row * DIM + tc * 4] =
                make_float4(acc[r][0], acc[r][1], acc[r][2], acc[r][3]);
            *(float4*)&Out[row * DIM + 64 + tc * 4] =
                make_float4(acc[r][4], acc[r][5], acc[r][6], acc[r][7]);
        }
    }
}

// ---------------- CSR gather aggregation ----------------
// One warp per destination node:
//   out[dst] = dinv[dst]^2 * tmp[dst] + sum_e norm_e * tmp[src_e] + bias
__global__ void k_gather(const float* __restrict__ tmp, const float* __restrict__ bias,
                         float* __restrict__ out) {
    int node = (int)((blockIdx.x * (unsigned)blockDim.x + threadIdx.x) >> 5);
    int lane = threadIdx.x & 31;
    if (node >= N_NODES) return;

    int beg = g_off[node];
    int end = g_off[node + 1];
    float dd = g_dinv[node];
    float self = dd * dd;

    float4 v = *(const float4*)&tmp[node * DIM + lane * 4];
    float4 acc = make_float4(v.x * self, v.y * self, v.z * self, v.w * self);

    int e = beg;
    for (; e + 1 < end; e += 2) {
        int2 m0 = g_edge[e];
        int2 m1 = g_edge[e + 1];
        float n0 = __int_as_float(m0.y);
        float n1 = __int_as_float(m1.y);
        float4 v0 = *(const float4*)&tmp[m0.x * DIM + lane * 4];
        float4 v1 = *(const float4*)&tmp[m1.x * DIM + lane * 4];
        acc.x += v0.x * n0 + v1.x * n1;
        acc.y += v0.y * n0 + v1.y * n1;
        acc.z += v0.z * n0 + v1.z * n1;
        acc.w += v0.w * n0 + v1.w * n1;
    }
    if (e < end) {
        int2 m0 = g_edge[e];
        float n0 = __int_as_float(m0.y);
        float4 v0 = *(const float4*)&tmp[m0.x * DIM + lane * 4];
        acc.x += v0.x * n0; acc.y += v0.y * n0;
        acc.z += v0.z * n0; acc.w += v0.w * n0;
    }

    float4 bb = *(const float4*)&bias[lane * 4];
    acc.x += bb.x; acc.y += bb.y; acc.z += bb.z; acc.w += bb.w;
    *(float4*)&out[node * DIM + lane * 4] = acc;
}

// ---------------- launch ----------------
extern "C" void kernel_launch(void* const* d_in, const int* in_sizes, int n_in,
                              void* d_out, int out_size) {
    const float* x  = (const float*)d_in[0];
    const int*   ei = (const int*)d_in[1];
    const float* W1 = (const float*)d_in[2];
    const float* b1 = (const float*)d_in[3];
    const float* W2 = (const float*)d_in[4];
    const float* b2 = (const float*)d_in[5];
    float* out = (float*)d_out;

    float* tmp_p; cudaGetSymbolAddress((void**)&tmp_p, g_tmp);
    float* h_p;   cudaGetSymbolAddress((void**)&h_p,   g_h);

    int nthr = 256;
    int nb_nodes  = (N_NODES + nthr - 1) / nthr;
    int nb_edges  = (N_EDGES + nthr - 1) / nthr;
    int nb_gemm   = (N_NODES + 127) / 128;
    int nb_gather = (N_NODES * 32 + nthr - 1) / nthr;

    // CSR build (by destination) + normalization
    k_zero_cnt<<<nb_nodes, nthr>>>();
    k_hist<<<nb_edges, nthr>>>(ei);
    k_dinv<<<nb_nodes, nthr>>>();
    k_scan<<<1, 1024>>>();
    k_scatter<<<nb_edges, nthr>>>(ei);

    // layer 1
    k_gemm<false><<<nb_gemm, nthr>>>(x, W1, tmp_p);
    k_gather<<<nb_gather, nthr>>>(tmp_p, b1, h_p);

    // layer 2
    k_gemm<true><<<nb_gemm, nthr>>>(h_p, W2, tmp_p);
    k_gather<<<nb_gather, nthr>>>(tmp_p, b2, out);
}

// round 3
// speedup vs baseline: 1.5988x; 1.4560x over previous
#include <cuda_runtime.h>

#define N_NODES 50000
#define N_EDGES 800000
#define DIM 128
#define SCAN_NB ((N_NODES + 255) / 256)   // 196 blocks

// Scratch (device globals)
__device__ int   g_cnt[N_NODES];
__device__ int   g_off[N_NODES + 1];
__device__ int   g_cur[N_NODES];
__device__ int   g_bsum[SCAN_NB];
__device__ int   g_boff[SCAN_NB];
__device__ float g_dinv[N_NODES];
__device__ int2  g_edge[N_EDGES];        // {src, norm bits} CSR-by-dst order
__device__ float g_tmp[N_NODES * DIM];
__device__ float g_h[N_NODES * DIM];

// ---------------- degree / CSR build ----------------
__global__ void k_zero_cnt() {
    int i = blockIdx.x * blockDim.x + threadIdx.x;
    if (i < N_NODES) g_cnt[i] = 0;
}

__global__ void k_hist(const int* __restrict__ ei) {
    int e = blockIdx.x * blockDim.x + threadIdx.x;
    if (e < N_EDGES) atomicAdd(&g_cnt[ei[N_EDGES + e]], 1);
}

__global__ void k_dinv() {
    int i = blockIdx.x * blockDim.x + threadIdx.x;
    if (i < N_NODES) g_dinv[i] = rsqrtf((float)(g_cnt[i] + 1));  // +1 self-loop
}

// Phase 1: per-block scan; g_off[i] = local exclusive prefix, g_bsum[b] = block total
__global__ void k_scan1() {
    __shared__ int s[256];
    int tid = threadIdx.x;
    int i = blockIdx.x * 256 + tid;
    int v = (i < N_NODES) ? g_cnt[i] : 0;
    s[tid] = v;
    __syncthreads();
#pragma unroll
    for (int d = 1; d < 256; d <<= 1) {
        int t = (tid >= d) ? s[tid - d] : 0;
        __syncthreads();
        s[tid] += t;
        __syncthreads();
    }
    if (i < N_NODES) g_off[i] = s[tid] - v;       // local exclusive
    if (tid == 255) g_bsum[blockIdx.x] = s[255];
}

// Phase 2: single small block scans the 196 block sums (exclusive)
__global__ void k_scan2() {
    __shared__ int s[SCAN_NB];
    int tid = threadIdx.x;
    int v = (tid < SCAN_NB) ? g_bsum[tid] : 0;
    if (tid < SCAN_NB) s[tid] = v;
    __syncthreads();
    for (int d = 1; d < SCAN_NB; d <<= 1) {
        int t = (tid >= d && tid < SCAN_NB) ? s[tid - d] : 0;
        __syncthreads();
        if (tid < SCAN_NB) s[tid] += t;
        __syncthreads();
    }
    if (tid < SCAN_NB) g_boff[tid] = s[tid] - v;  // exclusive
}

// Phase 3: add block offsets; init g_cur
__global__ void k_scan3() {
    int i = blockIdx.x * blockDim.x + threadIdx.x;
    if (i < N_NODES) {
        int o = g_off[i] + g_boff[blockIdx.x * 256 / 256 == 0 ? blockIdx.x : blockIdx.x];
        o = g_off[i] + g_boff[i >> 8];
        g_off[i] = o;
        g_cur[i] = o;
    }
    if (i == 0) g_off[N_NODES] = N_EDGES;   // total is known statically
}

__global__ void k_scatter(const int* __restrict__ ei) {
    int e = blockIdx.x * blockDim.x + threadIdx.x;
    if (e >= N_EDGES) return;
    int src = ei[e];
    int dst = ei[N_EDGES + e];
    int pos = atomicAdd(&g_cur[dst], 1);
    float norm = g_dinv[src] * g_dinv[dst];
    g_edge[pos] = make_int2(src, __float_as_int(norm));
}

// ---------------- GEMM: Out[N,128] = act(X)[N,128] @ W[128,128] ----------------
template<bool RELU>
__global__ void __launch_bounds__(256, 2)
k_gemm(const float* __restrict__ X, const float* __restrict__ W,
       float* __restrict__ Out) {
    __shared__ float sW[16][DIM];
    __shared__ float sX[16][132];

    int tid = threadIdx.x;
    int tc = tid & 15, tr = tid >> 4;
    int row0 = blockIdx.x * 128;

    float acc[8][8];
#pragma unroll
    for (int r = 0; r < 8; r++)
#pragma unroll
        for (int c = 0; c < 8; c++) acc[r][c] = 0.f;

    for (int kk = 0; kk < DIM; kk += 16) {
#pragma unroll
        for (int i = 0; i < 2; i++) {
            int lin = (i * 256 + tid) * 4;
            int k = lin >> 7, c = lin & 127;
            *(float4*)&sW[k][c] = *(const float4*)&W[(kk + k) * DIM + c];
        }
#pragma unroll
        for (int i = 0; i < 2; i++) {
            int lin = (i * 256 + tid) * 4;
            int r = lin >> 4, c = lin & 15;
            int row = row0 + r;
            float4 v = make_float4(0.f, 0.f, 0.f, 0.f);
            if (row < N_NODES) v = *(const float4*)&X[row * DIM + kk + c];
            if (RELU) {
                v.x = fmaxf(v.x, 0.f); v.y = fmaxf(v.y, 0.f);
                v.z = fmaxf(v.z, 0.f); v.w = fmaxf(v.w, 0.f);
            }
            sX[c + 0][r] = v.x; sX[c + 1][r] = v.y;
            sX[c + 2][r] = v.z; sX[c + 3][r] = v.w;
        }
        __syncthreads();

#pragma unroll
        for (int k = 0; k < 16; k++) {
            float a[8], b[8];
            *(float4*)&b[0] = *(float4*)&sW[k][tc * 4];
            *(float4*)&b[4] = *(float4*)&sW[k][tc * 4 + 64];
            *(float4*)&a[0] = *(float4*)&sX[k][tr * 8];
            *(float4*)&a[4] = *(float4*)&sX[k][tr * 8 + 4];
#pragma unroll
            for (int r = 0; r < 8; r++)
#pragma unroll
                for (int c = 0; c < 8; c++)
                    acc[r][c] += a[r] * b[c];
        }
        __syncthreads();
    }

#pragma unroll
    for (int r = 0; r < 8; r++) {
        int row = row0 + tr * 8 + r;
        if (row < N_NODES) {
            *(float4*)&Out[row * DIM + tc * 4] =
                make_float4(acc[r][0], acc[r][1], acc[r][2], acc[r][3]);
            *(float4*)&Out[row * DIM + 64 + tc * 4] =
                make_float4(acc[r][4], acc[r][5], acc[r][6], acc[r][7]);
        }
    }
}

// ---------------- CSR gather aggregation ----------------
// One warp per destination node, 4-edge unroll for MLP.
__global__ void k_gather(const float* __restrict__ tmp, const float* __restrict__ bias,
                         float* __restrict__ out) {
    int node = (int)((blockIdx.x * (unsigned)blockDim.x + threadIdx.x) >> 5);
    int lane = threadIdx.x & 31;
    if (node >= N_NODES) return;

    int beg = g_off[node];
    int end = g_off[node + 1];
    float dd = g_dinv[node];
    float self = dd * dd;

    float4 v = *(const float4*)&tmp[node * DIM + lane * 4];
    float4 acc = make_float4(v.x * self, v.y * self, v.z * self, v.w * self);

    int e = beg;
    for (; e + 3 < end; e += 4) {
        int2 m0 = g_edge[e + 0];
        int2 m1 = g_edge[e + 1];
        int2 m2 = g_edge[e + 2];
        int2 m3 = g_edge[e + 3];
        float4 v0 = *(const float4*)&tmp[m0.x * DIM + lane * 4];
        float4 v1 = *(const float4*)&tmp[m1.x * DIM + lane * 4];
        float4 v2 = *(const float4*)&tmp[m2.x * DIM + lane * 4];
        float4 v3 = *(const float4*)&tmp[m3.x * DIM + lane * 4];
        float n0 = __int_as_float(m0.y), n1 = __int_as_float(m1.y);
        float n2 = __int_as_float(m2.y), n3 = __int_as_float(m3.y);
        acc.x += v0.x * n0 + v1.x * n1 + v2.x * n2 + v3.x * n3;
        acc.y += v0.y * n0 + v1.y * n1 + v2.y * n2 + v3.y * n3;
        acc.z += v0.z * n0 + v1.z * n1 + v2.z * n2 + v3.z * n3;
        acc.w += v0.w * n0 + v1.w * n1 + v2.w * n2 + v3.w * n3;
    }
    for (; e < end; e++) {
        int2 m0 = g_edge[e];
        float n0 = __int_as_float(m0.y);
        float4 v0 = *(const float4*)&tmp[m0.x * DIM + lane * 4];
        acc.x += v0.x * n0; acc.y += v0.y * n0;
        acc.z += v0.z * n0; acc.w += v0.w * n0;
    }

    float4 bb = *(const float4*)&bias[lane * 4];
    acc.x += bb.x; acc.y += bb.y; acc.z += bb.z; acc.w += bb.w;
    *(float4*)&out[node * DIM + lane * 4] = acc;
}

// ---------------- launch ----------------
extern "C" void kernel_launch(void* const* d_in, const int* in_sizes, int n_in,
                              void* d_out, int out_size) {
    const float* x  = (const float*)d_in[0];
    const int*   ei = (const int*)d_in[1];
    const float* W1 = (const float*)d_in[2];
    const float* b1 = (const float*)d_in[3];
    const float* W2 = (const float*)d_in[4];
    const float* b2 = (const float*)d_in[5];
    float* out = (float*)d_out;

    float* tmp_p; cudaGetSymbolAddress((void**)&tmp_p, g_tmp);
    float* h_p;   cudaGetSymbolAddress((void**)&h_p,   g_h);

    int nthr = 256;
    int nb_nodes  = (N_NODES + nthr - 1) / nthr;
    int nb_edges  = (N_EDGES + nthr - 1) / nthr;
    int nb_gemm   = (N_NODES + 127) / 128;
    int nb_gather = (N_NODES * 32 + nthr - 1) / nthr;

    // CSR build (by destination) + normalization
    k_zero_cnt<<<nb_nodes, nthr>>>();
    k_hist<<<nb_edges, nthr>>>(ei);
    k_dinv<<<nb_nodes, nthr>>>();
    k_scan1<<<SCAN_NB, 256>>>();
    k_scan2<<<1, 256>>>();
    k_scan3<<<SCAN_NB, 256>>>();
    k_scatter<<<nb_edges, nthr>>>(ei);

    // layer 1
    k_gemm<false><<<nb_gemm, nthr>>>(x, W1, tmp_p);
    k_gather<<<nb_gather, nthr>>>(tmp_p, b1, h_p);

    // layer 2
    k_gemm<true><<<nb_gemm, nthr>>>(h_p, W2, tmp_p);
    k_gather<<<nb_gather, nthr>>>(tmp_p, b2, out);
}